// round 15
// baseline (speedup 1.0000x reference)
#include <cuda_runtime.h>
#include <cuda_bf16.h>
#include <mma.h>
#include <math.h>

using namespace nvcuda;

#define B_   128
#define T_   2048
#define NC   8            // chunks
#define CL   256          // chunk length
#define H_   512
#define NIT  16           // 16-timestep tiles per chunk

typedef unsigned long long ull;
typedef unsigned int u32;

// ---------------- device-global scratch ----------------
__device__ float g_yp [B_ * T_];            // pre-sigmoid partial y (no cross-chunk corr)
__device__ float g_eM [B_ * 7 * H_];        // local end states per chunk 0..6
__device__ float g_eD1[B_ * 7 * H_];
__device__ float g_eD2[B_ * 7 * H_];
__device__ ull   g_sM [B_ * 7 * 256];       // true start states chunks 1..7 (packed pairs)
__device__ ull   g_sD1[B_ * 7 * 256];
__device__ ull   g_sD2[B_ * 7 * 256];

// ---------------- helpers ----------------
__device__ __forceinline__ float sigm(float v) { return 1.0f / (1.0f + expf(-v)); }
__device__ __forceinline__ ull pack2(float lo, float hi) {
    ull d; asm("mov.b64 %0,{%1,%2};" : "=l"(d) : "f"(lo), "f"(hi)); return d;
}
__device__ __forceinline__ float2 asf2(ull v) {
    float2 r; asm("mov.b64 {%0,%1},%2;" : "=f"(r.x), "=f"(r.y) : "l"(v)); return r;
}
__device__ __forceinline__ ull fma2(ull a, ull b, ull c) {
    ull d; asm("fma.rn.f32x2 %0,%1,%2,%3;" : "=l"(d) : "l"(a), "l"(b), "l"(c)); return d;
}
__device__ __forceinline__ ull mul2(ull a, ull b) {
    ull d; asm("mul.rn.f32x2 %0,%1,%2;" : "=l"(d) : "l"(a), "l"(b)); return d;
}

// ---------------- smem layout (dynamic) ----------------
// W:  bf16 [br2][split2][k32][h512]            = 131072 B
// X:  bf16 [br2][split2][t16][k32]             =   8192 B
// I:  f32  [br2][t16][520]                     =  66560 B
// YW: f32  [warp16][t256]                      =  16384 B
#define OFF_W   0
#define OFF_X   131072
#define OFF_I   139264
#define IPAD    520
#define OFF_YW  205824
#define SMEM_TOTAL 222208

// ---------------- kernel 1: wmma projection + register scan, one chunk ----------------
__global__ void __launch_bounds__(512, 1) gemm_scan(
    const float* __restrict__ x,
    const float* __restrict__ W1, const float* __restrict__ b1,
    const float* __restrict__ W2, const float* __restrict__ b2,
    const float* __restrict__ Wo,
    const float* __restrict__ tm, const float* __restrict__ tn1,
    const float* __restrict__ tn2)
{
    extern __shared__ char sm[];
    __nv_bfloat16* Wp = (__nv_bfloat16*)(sm + OFF_W);   // (br*2+sp)*16384 + k*512 + h
    __nv_bfloat16* Xp = (__nv_bfloat16*)(sm + OFF_X);   // (br*2+sp)*512   + t*32 + k
    float*         Ip = (float*)(sm + OFF_I);           // br*16*IPAD + t*IPAD + h
    float*         YW = (float*)(sm + OFF_YW);          // w*256 + t

    const int bx   = blockIdx.x;            // b(9..3) | c(2..0)
    const int b    = bx >> 3;
    const int c    = bx & 7;
    const int tid  = threadIdx.x;
    const int wid  = tid >> 5;
    const int lane = tid & 31;
    const int h    = tid;                   // this thread's channel (512 threads, 512 ch)

    // ---- fold parameters for channel h ----
    const float al  = sigm(tm[h]);
    const float be1 = sigm(tn1[h]);
    const float be2 = sigm(tn2[h]);
    const float wo  = Wo[h];
    const float s1  = wo * (1.0f - al) * (1.0f - be1);
    const float s2  = wo * (1.0f - al) * (1.0f - be2);
    const float bias1 = s1 * b1[h];
    const float bias2 = s2 * b2[h];

    // ---- fold + split weights into smem (W[k][h] layout for matrix_b) ----
#pragma unroll
    for (int br = 0; br < 2; br++) {
        const float* W = br ? W2 : W1;
        const float  s = br ? s2 : s1;
#pragma unroll
        for (int k = 0; k < 20; k++) {
            float w = s * W[h * 20 + k];
            __nv_bfloat16 hb = __float2bfloat16_rn(w);
            float lof = w - __bfloat162float(hb);
            Wp[(br * 2 + 0) * 16384 + k * 512 + h] = hb;
            Wp[(br * 2 + 1) * 16384 + k * 512 + h] = __float2bfloat16_rn(lof);
        }
    }
    // zero W pad rows k=20..31
    for (int idx = tid; idx < 2 * 2 * 12 * 512; idx += 512) {
        int gsp = idx / (12 * 512);
        int rem = idx % (12 * 512);
        int k   = 20 + rem / 512;
        int hh  = rem % 512;
        Wp[gsp * 16384 + k * 512 + hh] = __float2bfloat16_rn(0.0f);
    }
    // zero X region once (pad cols k=20..31 stay zero forever)
    ((uint4*)(sm + OFF_X))[tid] = make_uint4(0, 0, 0, 0);
    __syncthreads();

    const float* gx = x + ((size_t)b * T_ + (size_t)c * CL) * 40;

    // ---- stage X tile 0 (element e of 640 = t*40+kk) ----
    for (int e = tid; e < 640; e += 512) {
        int t = e / 40, kk = e % 40;
        int br = (kk >= 20), k = kk - br * 20;
        float v = gx[e];
        __nv_bfloat16 hb = __float2bfloat16_rn(v);
        Xp[(br * 2 + 0) * 512 + t * 32 + k] = hb;
        Xp[(br * 2 + 1) * 512 + t * 32 + k] = __float2bfloat16_rn(v - __bfloat162float(hb));
    }
    __syncthreads();

    float D1 = 0.f, D2 = 0.f, M = 0.f;
    const int hb0 = wid * 32;

#pragma unroll 1
    for (int it = 0; it < NIT; it++) {
        // ---- GEMM phase: I[br][16t][512h] = X @ Wfold (split-bf16, 3 products) ----
#pragma unroll
        for (int br = 0; br < 2; br++) {
            wmma::fragment<wmma::accumulator, 16, 16, 16, float> c0, c1;
            wmma::fill_fragment(c0, 0.0f);
            wmma::fill_fragment(c1, 0.0f);
#pragma unroll
            for (int ks = 0; ks < 2; ks++) {
                wmma::fragment<wmma::matrix_a, 16, 16, 16, __nv_bfloat16, wmma::row_major> ahi, alo;
                wmma::load_matrix_sync(ahi, Xp + (br * 2 + 0) * 512 + ks * 16, 32);
                wmma::load_matrix_sync(alo, Xp + (br * 2 + 1) * 512 + ks * 16, 32);
                wmma::fragment<wmma::matrix_b, 16, 16, 16, __nv_bfloat16, wmma::row_major> bhi, blo;
                wmma::load_matrix_sync(bhi, Wp + (br * 2 + 0) * 16384 + ks * 16 * 512 + hb0, 512);
                wmma::load_matrix_sync(blo, Wp + (br * 2 + 1) * 16384 + ks * 16 * 512 + hb0, 512);
                wmma::mma_sync(c0, ahi, bhi, c0);
                wmma::mma_sync(c0, ahi, blo, c0);
                wmma::mma_sync(c0, alo, bhi, c0);
                wmma::load_matrix_sync(bhi, Wp + (br * 2 + 0) * 16384 + ks * 16 * 512 + hb0 + 16, 512);
                wmma::load_matrix_sync(blo, Wp + (br * 2 + 1) * 16384 + ks * 16 * 512 + hb0 + 16, 512);
                wmma::mma_sync(c1, ahi, bhi, c1);
                wmma::mma_sync(c1, ahi, blo, c1);
                wmma::mma_sync(c1, alo, bhi, c1);
            }
            wmma::store_matrix_sync(Ip + br * 16 * IPAD + hb0,      c0, IPAD, wmma::mem_row_major);
            wmma::store_matrix_sync(Ip + br * 16 * IPAD + hb0 + 16, c1, IPAD, wmma::mem_row_major);
        }
        __syncthreads();

        // ---- prefetch next X tile into registers (hide LDG under scan) ----
        float xv0 = 0.f, xv1 = 0.f;
        if (it + 1 < NIT) {
            xv0 = gx[(it + 1) * 640 + tid];
            if (tid < 128) xv1 = gx[(it + 1) * 640 + 512 + tid];
        }

        // ---- scan phase: 16 timesteps, thread = channel ----
        const float* I1 = Ip;
        const float* I2 = Ip + 16 * IPAD;
#pragma unroll
        for (int q = 0; q < 4; q++) {
            float p[4];
#pragma unroll
            for (int uu = 0; uu < 4; uu++) {
                const int tt = q * 4 + uu;
                float i1 = I1[tt * IPAD + tid] + bias1;
                float i2 = I2[tt * IPAD + tid] + bias2;
                D1 = fmaf(be1, D1, i1);
                D2 = fmaf(be2, D2, i2);
                M  = fmaf(al,  M,  D1 + D2);
                p[uu] = M;
            }
#pragma unroll
            for (int off = 16; off > 0; off >>= 1) {
#pragma unroll
                for (int uu = 0; uu < 4; uu++)
                    p[uu] += __shfl_down_sync(0xffffffffu, p[uu], off);
            }
            if (lane == 0)
                *(float4*)&YW[wid * 256 + it * 16 + q * 4] = make_float4(p[0], p[1], p[2], p[3]);
        }

        // ---- convert + store prefetched X ----
        if (it + 1 < NIT) {
            {
                int e = tid, t = e / 40, kk = e % 40;
                int br = (kk >= 20), k = kk - br * 20;
                __nv_bfloat16 hb = __float2bfloat16_rn(xv0);
                Xp[(br * 2 + 0) * 512 + t * 32 + k] = hb;
                Xp[(br * 2 + 1) * 512 + t * 32 + k] = __float2bfloat16_rn(xv0 - __bfloat162float(hb));
            }
            if (tid < 128) {
                int e = tid + 512, t = e / 40, kk = e % 40;
                int br = (kk >= 20), k = kk - br * 20;
                __nv_bfloat16 hb = __float2bfloat16_rn(xv1);
                Xp[(br * 2 + 0) * 512 + t * 32 + k] = hb;
                Xp[(br * 2 + 1) * 512 + t * 32 + k] = __float2bfloat16_rn(xv1 - __bfloat162float(hb));
            }
        }
        __syncthreads();
    }

    // ---- save end states for stitching ----
    if (c < 7) {
        const size_t si = ((size_t)b * 7 + c) * H_ + h;
        g_eM [si] = M;
        g_eD1[si] = D1;
        g_eD2[si] = D2;
    }
    // ---- combine 16 warp partials per timestep ----
    if (tid < 256) {
        float s = 0.f;
#pragma unroll
        for (int w = 0; w < 16; w++) s += YW[w * 256 + tid];
        g_yp[(size_t)b * T_ + c * CL + tid] = s;
    }
}

// stable S = (a^{d+1} - bb^{d+1})/(a - bb) given Ax=a^{d+1}, Bx=bb^{d+1}
__device__ __forceinline__ float seedS(float a, float bb, int d, float Ax, float Bx) {
    float diff = a - bb;
    if (fabsf(diff) > 0.04f * a) return (Ax - Bx) / diff;
    float lr  = log1pf((bb - a) / a);
    float den = -expm1f(lr);
    float ad  = Ax / a;
    if (den == 0.0f) return (float)(d + 1) * ad;
    float num = -expm1f((float)(d + 1) * lr);
    return ad * (num / den);
}

// ---------------- kernel 2: propagate true start states across chunks ----------------
__global__ void __launch_bounds__(256) combine_kernel(
    const float* __restrict__ tm, const float* __restrict__ tn1,
    const float* __restrict__ tn2)
{
    const int b = blockIdx.x;
    const int p = threadIdx.x;     // pair: channels 2p, 2p+1

    float sM[2]  = {0.f, 0.f}, sD1[2] = {0.f, 0.f}, sD2[2] = {0.f, 0.f};
    float aL[2], b1L[2], b2L[2], G1L[2], G2L[2];
#pragma unroll
    for (int hh = 0; hh < 2; hh++) {
        const int h = 2 * p + hh;
        float a   = sigm(tm[h]);
        float be1 = sigm(tn1[h]);
        float be2 = sigm(tn2[h]);
        float la = log2f(a), l1 = log2f(be1), l2 = log2f(be2);
        aL[hh]  = exp2f(256.0f * la);
        b1L[hh] = exp2f(256.0f * l1);
        b2L[hh] = exp2f(256.0f * l2);
        G1L[hh] = be1 * seedS(a, be1, 255, aL[hh], b1L[hh]);
        G2L[hh] = be2 * seedS(a, be2, 255, aL[hh], b2L[hh]);
    }

#pragma unroll
    for (int c = 0; c < 7; c++) {
        const size_t ei = ((size_t)b * 7 + c) * H_ + 2 * p;
#pragma unroll
        for (int hh = 0; hh < 2; hh++) {
            float eM  = g_eM [ei + hh];
            float eD1 = g_eD1[ei + hh];
            float eD2 = g_eD2[ei + hh];
            float nM  = aL[hh] * sM[hh] + G1L[hh] * sD1[hh] + G2L[hh] * sD2[hh] + eM;
            float nD1 = b1L[hh] * sD1[hh] + eD1;
            float nD2 = b2L[hh] * sD2[hh] + eD2;
            sM[hh] = nM; sD1[hh] = nD1; sD2[hh] = nD2;
        }
        const size_t si = ((size_t)b * 7 + c) * 256 + p;
        g_sM [si] = pack2(sM[0],  sM[1]);
        g_sD1[si] = pack2(sD1[0], sD1[1]);
        g_sD2[si] = pack2(sD2[0], sD2[1]);
    }
}

// ---------------- kernel 3: correction + sigmoid ----------------
__global__ void __launch_bounds__(256) corr_kernel(
    float* __restrict__ out, const float* __restrict__ bo,
    const float* __restrict__ tm, const float* __restrict__ tn1,
    const float* __restrict__ tn2)
{
    const int b   = blockIdx.x >> 3;
    const int c   = blockIdx.x & 7;
    const int tid = threadIdx.x;

    if (c == 0) {
        const size_t idx = (size_t)b * T_ + tid;
        out[idx] = 1.0f / (1.0f + expf(-(g_yp[idx] + bo[0])));
        return;
    }

    const int w    = tid >> 5;
    const int lane = tid & 31;
    const int p    = tid;

    float al0  = sigm(tm[2 * p]),  al1  = sigm(tm[2 * p + 1]);
    float be10 = sigm(tn1[2 * p]), be11 = sigm(tn1[2 * p + 1]);
    float be20 = sigm(tn2[2 * p]), be21 = sigm(tn2[2 * p + 1]);
    ull alp = pack2(al0, al1);
    ull b1p = pack2(be10, be11);
    ull b2p = pack2(be20, be21);
    ull A = alp, P1 = b1p, G1 = b1p, P2 = b2p, G2 = b2p;

    const size_t si = ((size_t)b * 7 + (c - 1)) * 256 + p;
    const ull M0  = g_sM [si];
    const ull D10 = g_sD1[si];
    const ull D20 = g_sD2[si];

    __shared__ float part[8][CL];

#pragma unroll 1
    for (int d = 0; d < CL; d++) {
        ull acc = fma2(A, M0, fma2(G1, D10, mul2(G2, D20)));
        A  = mul2(alp, A);
        P1 = mul2(b1p, P1);
        G1 = fma2(alp, G1, P1);
        P2 = mul2(b2p, P2);
        G2 = fma2(alp, G2, P2);
        float2 f = asf2(acc);
        float s = f.x + f.y;
#pragma unroll
        for (int off = 16; off > 0; off >>= 1)
            s += __shfl_down_sync(0xffffffffu, s, off);
        if (lane == 0) part[w][d] = s;
    }
    __syncthreads();

    {
        const size_t idx = (size_t)b * T_ + c * CL + tid;
        float s = bo[0];
#pragma unroll
        for (int w8 = 0; w8 < 8; w8++) s += part[w8][tid];
        s += g_yp[idx];
        out[idx] = 1.0f / (1.0f + expf(-s));
    }
}

// ---------------- launch ----------------
extern "C" void kernel_launch(void* const* d_in, const int* in_sizes, int n_in,
                              void* d_out, int out_size) {
    const float* x   = (const float*)d_in[0];
    const float* W1  = (const float*)d_in[1];
    const float* b1  = (const float*)d_in[2];
    const float* W2  = (const float*)d_in[3];
    const float* b2  = (const float*)d_in[4];
    const float* Wo  = (const float*)d_in[5];
    const float* bo  = (const float*)d_in[6];
    const float* tm  = (const float*)d_in[7];
    const float* tn1 = (const float*)d_in[8];
    const float* tn2 = (const float*)d_in[9];
    float* out = (float*)d_out;

    static int attr_done = 0;
    if (!attr_done) {
        cudaFuncSetAttribute(gemm_scan, cudaFuncAttributeMaxDynamicSharedMemorySize, SMEM_TOTAL);
        attr_done = 1;
    }
    gemm_scan<<<B_ * NC, 512, SMEM_TOTAL>>>(x, W1, b1, W2, b2, Wo, tm, tn1, tn2);
    combine_kernel<<<B_, 256>>>(tm, tn1, tn2);
    corr_kernel<<<B_ * NC, 256>>>(out, bo, tm, tn1, tn2);
}

// round 17
// speedup vs baseline: 2.5545x; 2.5545x over previous
#include <cuda_runtime.h>
#include <cuda_bf16.h>
#include <math.h>

#define B_   128
#define T_   2048
#define NC   8            // chunks
#define CL   256          // chunk length
#define H_   512
#define NIT  16           // 16-timestep tiles per chunk

typedef unsigned long long ull;
typedef unsigned int u32;

// ---------------- device-global scratch ----------------
__device__ float g_yp [B_ * T_];
__device__ float g_eM [B_ * 7 * H_];
__device__ float g_eD1[B_ * 7 * H_];
__device__ float g_eD2[B_ * 7 * H_];
__device__ ull   g_sM [B_ * 7 * 256];
__device__ ull   g_sD1[B_ * 7 * 256];
__device__ ull   g_sD2[B_ * 7 * 256];

// ---------------- helpers ----------------
__device__ __forceinline__ float sigm(float v) { return 1.0f / (1.0f + expf(-v)); }
__device__ __forceinline__ ull pack2(float lo, float hi) {
    ull d; asm("mov.b64 %0,{%1,%2};" : "=l"(d) : "f"(lo), "f"(hi)); return d;
}
__device__ __forceinline__ float2 asf2(ull v) {
    float2 r; asm("mov.b64 {%0,%1},%2;" : "=f"(r.x), "=f"(r.y) : "l"(v)); return r;
}
__device__ __forceinline__ ull fma2(ull a, ull b, ull c) {
    ull d; asm("fma.rn.f32x2 %0,%1,%2,%3;" : "=l"(d) : "l"(a), "l"(b), "l"(c)); return d;
}
__device__ __forceinline__ ull mul2(ull a, ull b) {
    ull d; asm("mul.rn.f32x2 %0,%1,%2;" : "=l"(d) : "l"(a), "l"(b)); return d;
}
__device__ __forceinline__ u32 bfpack(float a, float b) {   // low=a, high=b
    __nv_bfloat162 p = __floats2bfloat162_rn(a, b);
    return *reinterpret_cast<u32*>(&p);
}
// mma.sync m16n8k16 row.col f32 += bf16*bf16
__device__ __forceinline__ void mma16816(float* d, const uint4& a, const uint2& b) {
    asm volatile("mma.sync.aligned.m16n8k16.row.col.f32.bf16.bf16.f32 "
        "{%0,%1,%2,%3}, {%4,%5,%6,%7}, {%8,%9}, {%0,%1,%2,%3};"
        : "+f"(d[0]), "+f"(d[1]), "+f"(d[2]), "+f"(d[3])
        : "r"(a.x), "r"(a.y), "r"(a.z), "r"(a.w), "r"(b.x), "r"(b.y));
}

// ---------------- smem layout ----------------
// Wfrag: uint2 [frag8][slot64][lane32]      = 131072 B   frag = (br*2+split)*2+ks
// Xfrag: uint4 [frag8][lane32]              =   4096 B
// I    : f32  [br2][t16][520]               =  66560 B
// YW   : f32  [warp16][t256]                =  16384 B  (also reused as s1/s2 temp)
#define OFF_W   0
#define OFF_X   131072
#define OFF_I   135168
#define IPAD    520
#define OFF_YW  201728
#define SMEM_TOTAL 218112

// scatter one x element (chunk-tile coords) into Xfrag (both splits)
__device__ __forceinline__ void scatterX(char* sm, int e, float v) {
    int t  = e / 40, kk = e % 40;
    int br = (kk >= 20);
    int k  = kk - br * 20;
    int ks = k >> 4, cc = k & 15;
    int lane = ((t & 7) << 2) | ((cc & 7) >> 1);
    int r    = ((t >> 3) & 1) + 2 * (cc >> 3);
    int off  = lane * 16 + r * 4 + (cc & 1) * 2;
    __nv_bfloat16 hb = __float2bfloat16_rn(v);
    float lof = v - __bfloat162float(hb);
    *(__nv_bfloat16*)(sm + OFF_X + ((br * 2 + 0) * 2 + ks) * 512 + off) = hb;
    *(__nv_bfloat16*)(sm + OFF_X + ((br * 2 + 1) * 2 + ks) * 512 + off) = __float2bfloat16_rn(lof);
}

// ---------------- kernel 1: mma.sync projection + register scan ----------------
__global__ void __launch_bounds__(512, 1) gemm_scan(
    const float* __restrict__ x,
    const float* __restrict__ W1, const float* __restrict__ b1,
    const float* __restrict__ W2, const float* __restrict__ b2,
    const float* __restrict__ Wo,
    const float* __restrict__ tm, const float* __restrict__ tn1,
    const float* __restrict__ tn2)
{
    extern __shared__ char sm[];
    float* Ip = (float*)(sm + OFF_I);
    float* YW = (float*)(sm + OFF_YW);

    const int bx   = blockIdx.x;            // b(9..3) | c(2..0)
    const int b    = bx >> 3;
    const int c    = bx & 7;
    const int tid  = threadIdx.x;
    const int wid  = tid >> 5;
    const int lane = tid & 31;
    const int g    = lane >> 2;
    const int tg   = lane & 3;
    const int h    = tid;                   // scan channel

    // ---- per-channel folded params ----
    const float al  = sigm(tm[h]);
    const float be1 = sigm(tn1[h]);
    const float be2 = sigm(tn2[h]);
    const float wo  = Wo[h];
    const float s1  = wo * (1.0f - al) * (1.0f - be1);
    const float s2  = wo * (1.0f - al) * (1.0f - be2);
    const float bias1 = s1 * b1[h];
    const float bias2 = s2 * b2[h];

    // publish s1,s2 for the Wfrag build (temp use of YW region)
    YW[h] = s1;
    YW[512 + h] = s2;
    // zero Xfrag (pads stay zero forever)
    if (tid < 256) ((uint4*)(sm + OFF_X))[tid] = make_uint4(0, 0, 0, 0);
    __syncthreads();

    // ---- build Wfrag: fragment-linear split-bf16 weights ----
    // entries over (br,ks,slot,lane): 4*64*32 = 8192
    for (int e = tid; e < 8192; e += 512) {
        int ln = e & 31, slot = (e >> 5) & 63, f2 = e >> 11;
        int ks = f2 & 1, br = f2 >> 1;
        int gg = ln >> 2, tt = ln & 3;
        int hh = slot * 8 + gg;
        const float* W = br ? W2 : W1;
        float s = YW[br * 512 + hh];
        int k0 = ks * 16 + 2 * tt;
        float w0 = (k0     < 20) ? s * W[hh * 20 + k0]     : 0.f;
        float w1 = (k0 + 1 < 20) ? s * W[hh * 20 + k0 + 1] : 0.f;
        float w8 = (k0 + 8 < 20) ? s * W[hh * 20 + k0 + 8] : 0.f;
        float w9 = (k0 + 9 < 20) ? s * W[hh * 20 + k0 + 9] : 0.f;
        __nv_bfloat16 h0 = __float2bfloat16_rn(w0), h1 = __float2bfloat16_rn(w1);
        __nv_bfloat16 h8 = __float2bfloat16_rn(w8), h9 = __float2bfloat16_rn(w9);
        uint2 bhi, blo;
        bhi.x = bfpack(__bfloat162float(h0), __bfloat162float(h1));   // exact repack
        bhi.y = bfpack(__bfloat162float(h8), __bfloat162float(h9));
        blo.x = bfpack(w0 - __bfloat162float(h0), w1 - __bfloat162float(h1));
        blo.y = bfpack(w8 - __bfloat162float(h8), w9 - __bfloat162float(h9));
        int fhi = (br * 2 + 0) * 2 + ks;
        int flo = (br * 2 + 1) * 2 + ks;
        *(uint2*)(sm + OFF_W + ((fhi * 64 + slot) * 32 + ln) * 8) = bhi;
        *(uint2*)(sm + OFF_W + ((flo * 64 + slot) * 32 + ln) * 8) = blo;
    }
    __syncthreads();

    const float* gx = x + ((size_t)b * T_ + (size_t)c * CL) * 40;

    // ---- stage X tile 0 ----
    for (int e = tid; e < 640; e += 512) scatterX(sm, e, gx[e]);
    __syncthreads();

    float D1 = 0.f, D2 = 0.f, M = 0.f;

#pragma unroll 1
    for (int it = 0; it < NIT; it++) {
        // ---- GEMM phase ----
        uint4 af[8];
#pragma unroll
        for (int f = 0; f < 8; f++)
            af[f] = *(uint4*)(sm + OFF_X + f * 512 + lane * 16);

#pragma unroll
        for (int br = 0; br < 2; br++) {
#pragma unroll
            for (int s4 = 0; s4 < 4; s4++) {
                const int slot = wid * 4 + s4;
                float d[4] = {0.f, 0.f, 0.f, 0.f};
#pragma unroll
                for (int ks = 0; ks < 2; ks++) {
                    const int fhi = (br * 2 + 0) * 2 + ks;
                    const int flo = (br * 2 + 1) * 2 + ks;
                    uint2 bhi = *(uint2*)(sm + OFF_W + ((fhi * 64 + slot) * 32 + lane) * 8);
                    uint2 blo = *(uint2*)(sm + OFF_W + ((flo * 64 + slot) * 32 + lane) * 8);
                    mma16816(d, af[fhi], bhi);
                    mma16816(d, af[fhi], blo);
                    mma16816(d, af[flo], bhi);
                }
                const int h0 = slot * 8 + 2 * tg;
                float* Irow = Ip + br * 16 * IPAD;
                *(float2*)&Irow[g * IPAD + h0]       = make_float2(d[0], d[1]);
                *(float2*)&Irow[(g + 8) * IPAD + h0] = make_float2(d[2], d[3]);
            }
        }
        __syncthreads();

        // ---- prefetch next tile's raw x into registers ----
        float xv0 = 0.f, xv1 = 0.f;
        if (it + 1 < NIT) {
            xv0 = gx[(it + 1) * 640 + tid];
            if (tid < 128) xv1 = gx[(it + 1) * 640 + 512 + tid];
        }

        // ---- scan phase: 16 timesteps, thread = channel ----
#pragma unroll
        for (int q = 0; q < 4; q++) {
            float p[4];
#pragma unroll
            for (int uu = 0; uu < 4; uu++) {
                const int tt = q * 4 + uu;
                float i1 = Ip[tt * IPAD + tid] + bias1;
                float i2 = Ip[16 * IPAD + tt * IPAD + tid] + bias2;
                D1 = fmaf(be1, D1, i1);
                D2 = fmaf(be2, D2, i2);
                M  = fmaf(al,  M,  D1 + D2);
                p[uu] = M;
            }
#pragma unroll
            for (int off = 16; off > 0; off >>= 1) {
#pragma unroll
                for (int uu = 0; uu < 4; uu++)
                    p[uu] += __shfl_down_sync(0xffffffffu, p[uu], off);
            }
            if (lane == 0)
                *(float4*)&YW[wid * 256 + it * 16 + q * 4] = make_float4(p[0], p[1], p[2], p[3]);
        }

        // ---- scatter prefetched x into Xfrag ----
        if (it + 1 < NIT) {
            scatterX(sm, tid, xv0);
            if (tid < 128) scatterX(sm, 512 + tid, xv1);
        }
        __syncthreads();
    }

    // ---- save end states ----
    if (c < 7) {
        const size_t si = ((size_t)b * 7 + c) * H_ + h;
        g_eM [si] = M;
        g_eD1[si] = D1;
        g_eD2[si] = D2;
    }
    // ---- combine 16 warp partials per timestep ----
    if (tid < 256) {
        float s = 0.f;
#pragma unroll
        for (int w = 0; w < 16; w++) s += YW[w * 256 + tid];
        g_yp[(size_t)b * T_ + c * CL + tid] = s;
    }
}

// stable S = (a^{d+1} - bb^{d+1})/(a - bb)
__device__ __forceinline__ float seedS(float a, float bb, int d, float Ax, float Bx) {
    float diff = a - bb;
    if (fabsf(diff) > 0.04f * a) return (Ax - Bx) / diff;
    float lr  = log1pf((bb - a) / a);
    float den = -expm1f(lr);
    float ad  = Ax / a;
    if (den == 0.0f) return (float)(d + 1) * ad;
    float num = -expm1f((float)(d + 1) * lr);
    return ad * (num / den);
}

// ---------------- kernel 2: propagate true start states across chunks ----------------
__global__ void __launch_bounds__(256) combine_kernel(
    const float* __restrict__ tm, const float* __restrict__ tn1,
    const float* __restrict__ tn2)
{
    const int b = blockIdx.x;
    const int p = threadIdx.x;

    float sM[2]  = {0.f, 0.f}, sD1[2] = {0.f, 0.f}, sD2[2] = {0.f, 0.f};
    float aL[2], b1L[2], b2L[2], G1L[2], G2L[2];
#pragma unroll
    for (int hh = 0; hh < 2; hh++) {
        const int h = 2 * p + hh;
        float a   = sigm(tm[h]);
        float be1 = sigm(tn1[h]);
        float be2 = sigm(tn2[h]);
        float la = log2f(a), l1 = log2f(be1), l2 = log2f(be2);
        aL[hh]  = exp2f(256.0f * la);
        b1L[hh] = exp2f(256.0f * l1);
        b2L[hh] = exp2f(256.0f * l2);
        G1L[hh] = be1 * seedS(a, be1, 255, aL[hh], b1L[hh]);
        G2L[hh] = be2 * seedS(a, be2, 255, aL[hh], b2L[hh]);
    }

#pragma unroll
    for (int c = 0; c < 7; c++) {
        const size_t ei = ((size_t)b * 7 + c) * H_ + 2 * p;
#pragma unroll
        for (int hh = 0; hh < 2; hh++) {
            float eM  = g_eM [ei + hh];
            float eD1 = g_eD1[ei + hh];
            float eD2 = g_eD2[ei + hh];
            float nM  = aL[hh] * sM[hh] + G1L[hh] * sD1[hh] + G2L[hh] * sD2[hh] + eM;
            float nD1 = b1L[hh] * sD1[hh] + eD1;
            float nD2 = b2L[hh] * sD2[hh] + eD2;
            sM[hh] = nM; sD1[hh] = nD1; sD2[hh] = nD2;
        }
        const size_t si = ((size_t)b * 7 + c) * 256 + p;
        g_sM [si] = pack2(sM[0],  sM[1]);
        g_sD1[si] = pack2(sD1[0], sD1[1]);
        g_sD2[si] = pack2(sD2[0], sD2[1]);
    }
}

// ---------------- kernel 3: correction + sigmoid ----------------
__global__ void __launch_bounds__(256) corr_kernel(
    float* __restrict__ out, const float* __restrict__ bo,
    const float* __restrict__ tm, const float* __restrict__ tn1,
    const float* __restrict__ tn2)
{
    const int b   = blockIdx.x >> 3;
    const int c   = blockIdx.x & 7;
    const int tid = threadIdx.x;

    if (c == 0) {
        const size_t idx = (size_t)b * T_ + tid;
        out[idx] = 1.0f / (1.0f + expf(-(g_yp[idx] + bo[0])));
        return;
    }

    const int w    = tid >> 5;
    const int lane = tid & 31;
    const int p    = tid;

    float al0  = sigm(tm[2 * p]),  al1  = sigm(tm[2 * p + 1]);
    float be10 = sigm(tn1[2 * p]), be11 = sigm(tn1[2 * p + 1]);
    float be20 = sigm(tn2[2 * p]), be21 = sigm(tn2[2 * p + 1]);
    ull alp = pack2(al0, al1);
    ull b1p = pack2(be10, be11);
    ull b2p = pack2(be20, be21);
    ull A = alp, P1 = b1p, G1 = b1p, P2 = b2p, G2 = b2p;

    const size_t si = ((size_t)b * 7 + (c - 1)) * 256 + p;
    const ull M0  = g_sM [si];
    const ull D10 = g_sD1[si];
    const ull D20 = g_sD2[si];

    __shared__ float part[8][CL];

#pragma unroll 1
    for (int d = 0; d < CL; d++) {
        ull acc = fma2(A, M0, fma2(G1, D10, mul2(G2, D20)));
        A  = mul2(alp, A);
        P1 = mul2(b1p, P1);
        G1 = fma2(alp, G1, P1);
        P2 = mul2(b2p, P2);
        G2 = fma2(alp, G2, P2);
        float2 f = asf2(acc);
        float s = f.x + f.y;
#pragma unroll
        for (int off = 16; off > 0; off >>= 1)
            s += __shfl_down_sync(0xffffffffu, s, off);
        if (lane == 0) part[w][d] = s;
    }
    __syncthreads();

    {
        const size_t idx = (size_t)b * T_ + c * CL + tid;
        float s = bo[0];
#pragma unroll
        for (int w8 = 0; w8 < 8; w8++) s += part[w8][tid];
        s += g_yp[idx];
        out[idx] = 1.0f / (1.0f + expf(-s));
    }
}

// ---------------- launch ----------------
extern "C" void kernel_launch(void* const* d_in, const int* in_sizes, int n_in,
                              void* d_out, int out_size) {
    const float* x   = (const float*)d_in[0];
    const float* W1  = (const float*)d_in[1];
    const float* b1  = (const float*)d_in[2];
    const float* W2  = (const float*)d_in[3];
    const float* b2  = (const float*)d_in[4];
    const float* Wo  = (const float*)d_in[5];
    const float* bo  = (const float*)d_in[6];
    const float* tm  = (const float*)d_in[7];
    const float* tn1 = (const float*)d_in[8];
    const float* tn2 = (const float*)d_in[9];
    float* out = (float*)d_out;

    static int attr_done = 0;
    if (!attr_done) {
        cudaFuncSetAttribute(gemm_scan, cudaFuncAttributeMaxDynamicSharedMemorySize, SMEM_TOTAL);
        attr_done = 1;
    }
    gemm_scan<<<B_ * NC, 512, SMEM_TOTAL>>>(x, W1, b1, W2, b2, Wo, tm, tn1, tn2);
    combine_kernel<<<B_, 256>>>(tm, tn1, tn2);
    corr_kernel<<<B_ * NC, 256>>>(out, bo, tm, tn1, tn2);
}